// round 13
// baseline (speedup 1.0000x reference)
#include <cuda_runtime.h>
#include <cuda_bf16.h>
#include <cuda_fp16.h>
#include <math.h>
#include <stdint.h>

// Problem constants
#define NN_ 10000
#define DD_ 128
#define KSEL 5000

// GEMM config
#define NJT 79              // j tiles of 128
#define KSPL 16             // k splits
#define NUNITS (NJT * KSPL) // 1264
#define NCHUNK 313          // 32-i chunks covering 10016
#define GRID_GEMM 148
#define ZSCALE 2048.0f
#define INV_ZSCALE (1.0f / 2048.0f)

// deg partials
#define DEG_CHUNKS 16
#define DEG_ROWS   625

// Output layout (float32, reference return order)
#define OFF_XPOOL   ((size_t)0)
#define OFF_ADJ     ((size_t)KSEL * DD_)
#define OFF_MOTIF   (OFF_ADJ + (size_t)KSEL * KSEL)
#define OFF_SCORES  (OFF_MOTIF + (size_t)KSEL * KSEL)
#define OFF_TOPIDX  (OFF_SCORES + (size_t)NN_)

// ---------------- device scratch ----------------
__device__ float g_WT[DD_ * DD_];
__device__ float g_part[DEG_CHUNKS * NN_];
__device__ float g_dinv[NN_];
__device__ float g_z[(size_t)NN_ * DD_];            // plain layout (epilogue +I term)
__device__ uint4 g_zfrag[(size_t)NCHUNK * 1024];    // fp16 fragment layout hi/lo (~5MB)
__device__ float g_Upart[KSPL][(size_t)NN_ * DD_];  // split-K partials
__device__ float g_h[(size_t)NN_ * DD_];
__device__ float g_scores[NN_];
__device__ int   g_topidx[KSEL];
__device__ int   g_cnt[NJT];                        // per-j-tile completion counters

// ---------------- helpers ----------------
__device__ __forceinline__ void cp16(void* smem, const void* gmem) {
    unsigned a = (unsigned)__cvta_generic_to_shared(smem);
    asm volatile("cp.async.ca.shared.global [%0], [%1], 16;\n" :: "r"(a), "l"(gmem) : "memory");
}
__device__ __forceinline__ void cp_commit() {
    asm volatile("cp.async.commit_group;\n" ::: "memory");
}
template<int NPEND>
__device__ __forceinline__ void cp_wait() {
    asm volatile("cp.async.wait_group %0;\n" :: "n"(NPEND) : "memory");
}
__device__ __forceinline__ uint32_t pack2h(__half a, __half b) {
    return (uint32_t)__half_as_ushort(a) | ((uint32_t)__half_as_ushort(b) << 16);
}
// D(16x8,f32) += A(16x16,f16) * B(16x8,f16)
__device__ __forceinline__ void mma16(float4& d, const uint4& a, const uint2& b) {
    asm volatile(
        "mma.sync.aligned.m16n8k16.row.col.f32.f16.f16.f32 "
        "{%0,%1,%2,%3}, {%4,%5,%6,%7}, {%8,%9}, {%0,%1,%2,%3};\n"
        : "+f"(d.x), "+f"(d.y), "+f"(d.z), "+f"(d.w)
        : "r"(a.x), "r"(a.y), "r"(a.z), "r"(a.w), "r"(b.x), "r"(b.y));
}

// ---------------- K1: deg column sums ----------------
__global__ void k_deg_part(const float* __restrict__ motif) {
    int j = blockIdx.x * 256 + threadIdx.x;
    int c = blockIdx.y;
    if (j >= NN_) return;
    int i0 = c * DEG_ROWS, i1 = i0 + DEG_ROWS;
    float s0 = 0.f, s1 = 0.f, s2 = 0.f, s3 = 0.f;
    int i = i0;
    for (; i + 4 <= i1; i += 4) {
        s0 += motif[(size_t)(i    ) * NN_ + j];
        s1 += motif[(size_t)(i + 1) * NN_ + j];
        s2 += motif[(size_t)(i + 2) * NN_ + j];
        s3 += motif[(size_t)(i + 3) * NN_ + j];
    }
    for (; i < i1; ++i) s0 += motif[(size_t)i * NN_ + j];
    g_part[c * NN_ + j] = (s0 + s1) + (s2 + s3);
}

// ---------------- K1b: fused prelude — dinv finalize + W transpose + cnt zero ----------------
__global__ __launch_bounds__(256) void k_fin(const float* __restrict__ W) {
    int b = blockIdx.x;
    int tid = threadIdx.x;
    if (b < 40) {                            // dinv
        int j = b * 256 + tid;
        if (j < NN_) {
            float d = 1.0f;
            #pragma unroll
            for (int c = 0; c < DEG_CHUNKS; ++c) d += g_part[c * NN_ + j];
            g_dinv[j] = 1.0f / sqrtf(d);
        }
    } else {                                 // W transpose (64 blocks x 256)
        int t = (b - 40) * 256 + tid;
        int e = t >> 7, d = t & 127;
        g_WT[e * DD_ + d] = W[d * DD_ + e];
        if (b == 40 && tid < NJT) g_cnt[tid] = 0;
    }
}

// ---------------- K2: z = dinv*(x@W^T); emit plain + fp16 fragment hi/lo ----------------
#define ZROWS 16
__global__ __launch_bounds__(128) void k_z(const float* __restrict__ x) {
    __shared__ float xst[DD_][20];       // [e][r], pad 20
    __shared__ __half zf[4096];          // fragment staging (8KB)

    int i0 = blockIdx.x * ZROWS;
    int tid = threadIdx.x;               // = d

    for (int l = tid; l < ZROWS * DD_; l += 128) {
        int r = l >> 7, e = l & 127;
        xst[e][r] = (i0 + r < NN_) ? x[(size_t)(i0 + r) * DD_ + e] : 0.f;
    }
    __syncthreads();

    float acc[ZROWS];
    #pragma unroll
    for (int r = 0; r < ZROWS; ++r) acc[r] = 0.f;
    #pragma unroll 4
    for (int e = 0; e < DD_; ++e) {
        float w = g_WT[e * DD_ + tid];
        float4 a0 = *(const float4*)&xst[e][0];
        float4 a1 = *(const float4*)&xst[e][4];
        float4 a2 = *(const float4*)&xst[e][8];
        float4 a3 = *(const float4*)&xst[e][12];
        acc[0]  += a0.x * w;  acc[1]  += a0.y * w;  acc[2]  += a0.z * w;  acc[3]  += a0.w * w;
        acc[4]  += a1.x * w;  acc[5]  += a1.y * w;  acc[6]  += a1.z * w;  acc[7]  += a1.w * w;
        acc[8]  += a2.x * w;  acc[9]  += a2.y * w;  acc[10] += a2.z * w;  acc[11] += a2.w * w;
        acc[12] += a3.x * w;  acc[13] += a3.y * w;  acc[14] += a3.z * w;  acc[15] += a3.w * w;
    }

    int nt = tid >> 3, nc = tid & 7;
    #pragma unroll
    for (int r = 0; r < ZROWS; ++r) {
        int i = i0 + r;
        float Z = 0.f;
        if (i < NN_) {
            float zv = g_dinv[i] * acc[r];
            g_z[(size_t)i * DD_ + tid] = zv;
            Z = zv * ZSCALE;
        }
        __half zh = __float2half_rn(Z);
        __half zl = __float2half_rn(Z - __half2float(zh));
        int kk = i & 15;
        int lane = nc * 4 + ((kk & 7) >> 1);
        int reg = kk >> 3, h = kk & 1;
        int off = nt * 128 + lane * 4 + reg * 2 + h;
        zf[off]        = zh;
        zf[off + 2048] = zl;
    }
    __syncthreads();

    int ks = blockIdx.x & 1;
    int chunk = i0 >> 5;
    const uint4* zsrc = (const uint4*)zf;
    #pragma unroll
    for (int q = 0; q < 4; ++q) {
        int idx = tid + q * 128;          // 0..511
        int region = idx >> 4;            // term*16 + nt
        int part = idx & 15;
        g_zfrag[(size_t)chunk * 1024 + (region * 2 + ks) * 16 + part] = zsrc[idx];
    }
}

// ---------------- K3: persistent mma.sync fp16x3 GEMM + fused split-K epilogue ----------------
#define STAGE_BYTES 32768
#define NSTAGE 3
#define GEMM_SMEM   (NSTAGE * STAGE_BYTES)

__device__ __forceinline__ float ldm(const float* __restrict__ m, int i, int j) {
    return (i < NN_ && j < NN_) ? __ldg(&m[(size_t)i * NN_ + j]) : 0.f;
}

__device__ __forceinline__ void prefetchA(float* apre, const float* __restrict__ motif,
                                          int ic, int J0, int w, int g, int c0) {
    int jb = J0 + w * 16 + g;
    #pragma unroll
    for (int ks = 0; ks < 2; ++ks) {
        int ib = ic * 32 + ks * 16 + c0;
        apre[ks * 8 + 0] = ldm(motif, ib,     jb);
        apre[ks * 8 + 1] = ldm(motif, ib + 1, jb);
        apre[ks * 8 + 2] = ldm(motif, ib,     jb + 8);
        apre[ks * 8 + 3] = ldm(motif, ib + 1, jb + 8);
        apre[ks * 8 + 4] = ldm(motif, ib + 8, jb);
        apre[ks * 8 + 5] = ldm(motif, ib + 9, jb);
        apre[ks * 8 + 6] = ldm(motif, ib + 8, jb + 8);
        apre[ks * 8 + 7] = ldm(motif, ib + 9, jb + 8);
    }
}

__device__ __forceinline__ void stsA(char* As, const float* apre, int w, int l) {
    #pragma unroll
    for (int ks = 0; ks < 2; ++ks) {
        uint32_t ph[4], pl[4];
        #pragma unroll
        for (int q = 0; q < 4; ++q) {
            float v0 = apre[ks * 8 + q * 2], v1 = apre[ks * 8 + q * 2 + 1];
            __half h0 = __float2half_rn(v0);
            __half h1 = __float2half_rn(v1);
            __half l0 = __float2half_rn(v0 - __half2float(h0));
            __half l1 = __float2half_rn(v1 - __half2float(h1));
            ph[q] = pack2h(h0, h1);
            pl[q] = pack2h(l0, l1);
        }
        *(uint4*)(As +        (w * 2 + ks) * 512 + l * 16) = make_uint4(ph[0], ph[1], ph[2], ph[3]);
        *(uint4*)(As + 8192 + (w * 2 + ks) * 512 + l * 16) = make_uint4(pl[0], pl[1], pl[2], pl[3]);
    }
}

__device__ __forceinline__ void loadB_async(char* sm, int stage, int chunk, int tid) {
    const char* src = (const char*)g_zfrag + (size_t)chunk * 16384;
    char* Bs = sm + stage * STAGE_BYTES + 16384;
    #pragma unroll
    for (int q = 0; q < 4; ++q)
        cp16(Bs + (tid + q * 256) * 16, src + (size_t)(tid + q * 256) * 16);
    cp_commit();
}

__global__ __launch_bounds__(256, 1) void k_gemm_mma(
    const float* __restrict__ motif,
    const float* __restrict__ b_gcn,
    const float* __restrict__ w_score,
    const float* __restrict__ b_score,
    float* __restrict__ out_scores)
{
    extern __shared__ char sm[];
    __shared__ int sh_old;
    int tid = threadIdx.x;
    int w = tid >> 5, l = tid & 31;
    int wm = w & 1, wn = w >> 1;
    int g = l >> 2, cb = l & 3;
    int c0 = cb * 2;

    for (int u = blockIdx.x; u < NUNITS; u += GRID_GEMM) {
        int jt = u % NJT, ksp = u / NJT;
        int J0 = jt * 128;
        int ch0 = (ksp * NCHUNK) / KSPL;
        int ch1 = ((ksp + 1) * NCHUNK) / KSPL;
        int nch = ch1 - ch0;

        float4 acc[4][4];
        #pragma unroll
        for (int a = 0; a < 4; ++a)
            #pragma unroll
            for (int b = 0; b < 4; ++b) acc[a][b] = make_float4(0.f, 0.f, 0.f, 0.f);

        float apre[16];
        prefetchA(apre, motif, ch0, J0, w, g, c0);
        loadB_async(sm, 0, ch0, tid);
        if (nch > 1) loadB_async(sm, 1, ch0 + 1, tid);
        stsA(sm, apre, w, l);
        if (nch > 1) prefetchA(apre, motif, ch0 + 1, J0, w, g, c0);

        for (int cc = 0; cc < nch; ++cc) {
            int s = cc % NSTAGE;
            char* As = sm + s * STAGE_BYTES;
            char* Bs = As + 16384;

            if (cc + 1 < nch) stsA(sm + ((cc + 1) % NSTAGE) * STAGE_BYTES, apre, w, l);
            if (cc + 2 < nch) prefetchA(apre, motif, ch0 + cc + 2, J0, w, g, c0);

            if (cc + 1 < nch) cp_wait<1>(); else cp_wait<0>();
            __syncthreads();

            if (cc + 2 < nch) loadB_async(sm, (cc + 2) % NSTAGE, ch0 + cc + 2, tid);

            // MMA: 2 k-steps x 3 split terms (term-outer: independent acc chains)
            #pragma unroll
            for (int ks = 0; ks < 2; ++ks) {
                uint2 bh[4], bl[4];
                uint4 ah[4], al[4];
                #pragma unroll
                for (int ntl = 0; ntl < 4; ++ntl) {
                    int nto = ((wn * 4 + ntl) * 2 + ks) * 256 + l * 8;
                    bh[ntl] = *(const uint2*)(Bs + nto);
                    bl[ntl] = *(const uint2*)(Bs + 8192 + nto);
                }
                #pragma unroll
                for (int mtl = 0; mtl < 4; ++mtl) {
                    int mto = ((wm * 4 + mtl) * 2 + ks) * 512 + l * 16;
                    ah[mtl] = *(const uint4*)(As + mto);
                    al[mtl] = *(const uint4*)(As + 8192 + mto);
                }
                #pragma unroll
                for (int mtl = 0; mtl < 4; ++mtl)
                    #pragma unroll
                    for (int ntl = 0; ntl < 4; ++ntl)
                        mma16(acc[mtl][ntl], ah[mtl], bh[ntl]);
                #pragma unroll
                for (int mtl = 0; mtl < 4; ++mtl)
                    #pragma unroll
                    for (int ntl = 0; ntl < 4; ++ntl)
                        mma16(acc[mtl][ntl], ah[mtl], bl[ntl]);
                #pragma unroll
                for (int mtl = 0; mtl < 4; ++mtl)
                    #pragma unroll
                    for (int ntl = 0; ntl < 4; ++ntl)
                        mma16(acc[mtl][ntl], al[mtl], bh[ntl]);
            }
        }

        // write partials (rescale by 1/2048)
        float* Up = g_Upart[ksp];
        #pragma unroll
        for (int mtl = 0; mtl < 4; ++mtl) {
            int r0 = J0 + wm * 64 + mtl * 16 + g;
            #pragma unroll
            for (int ntl = 0; ntl < 4; ++ntl) {
                int d0 = wn * 32 + ntl * 8 + cb * 2;
                float4 a = acc[mtl][ntl];
                if (r0 < NN_)
                    *(float2*)&Up[(size_t)r0 * 128 + d0] =
                        make_float2(a.x * INV_ZSCALE, a.y * INV_ZSCALE);
                if (r0 + 8 < NN_)
                    *(float2*)&Up[(size_t)(r0 + 8) * 128 + d0] =
                        make_float2(a.z * INV_ZSCALE, a.w * INV_ZSCALE);
            }
        }

        // release: make partials visible, then count completion for this j-tile
        __threadfence();
        __syncthreads();
        if (tid == 0) sh_old = atomicAdd(&g_cnt[jt], 1);
        __syncthreads();

        if (sh_old == KSPL - 1) {
            // acquire: all 16 partials for jt are visible — fused epilogue
            __threadfence();
            float4 bg = *(const float4*)&b_gcn[l * 4];
            float4 ws = *(const float4*)&w_score[l * 4];
            float b0 = b_score[0];
            #pragma unroll 2
            for (int rr = 0; rr < 16; ++rr) {
                int j = J0 + w * 16 + rr;
                if (j >= NN_) break;
                size_t off = (size_t)j * DD_ + l * 4;
                float4 u = *(const float4*)&g_z[off];       // +I term
                #pragma unroll
                for (int s2 = 0; s2 < KSPL; ++s2) {
                    float4 p = *(const float4*)&g_Upart[s2][off];
                    u.x += p.x; u.y += p.y; u.z += p.z; u.w += p.w;
                }
                float dj = g_dinv[j];
                float4 hh;
                hh.x = tanhf(dj * u.x + bg.x);
                hh.y = tanhf(dj * u.y + bg.y);
                hh.z = tanhf(dj * u.z + bg.z);
                hh.w = tanhf(dj * u.w + bg.w);
                *(float4*)&g_h[off] = hh;
                float ss = hh.x * ws.x + hh.y * ws.y + hh.z * ws.z + hh.w * ws.w;
                #pragma unroll
                for (int o = 16; o; o >>= 1) ss += __shfl_down_sync(0xffffffffu, ss, o);
                if (l == 0) {
                    float sc = ss + b0;
                    g_scores[j] = sc;
                    out_scores[j] = sc;
                }
            }
        }
        __syncthreads();   // protect smem stage reuse by next unit
    }
}

// ---------------- K5: exact top-k selection ----------------
__global__ __launch_bounds__(1024) void k_select(float* __restrict__ out_topidx_f) {
    __shared__ unsigned keys[NN_];
    __shared__ unsigned hist[256];
    __shared__ unsigned sc[1024];
    __shared__ unsigned sh_prefix, sh_r, sh_cg;
    int tid = threadIdx.x;

    for (int i = tid; i < NN_; i += 1024) {
        unsigned u = __float_as_uint(g_scores[i]);
        u = (u & 0x80000000u) ? ~u : (u | 0x80000000u);
        keys[i] = u;
    }
    if (tid == 0) { sh_prefix = 0u; sh_r = KSEL; sh_cg = 0u; }
    __syncthreads();

    for (int p = 3; p >= 0; --p) {
        if (tid < 256) hist[tid] = 0u;
        __syncthreads();
        unsigned msk  = (p == 3) ? 0u : (0xFFFFFFFFu << (8 * (p + 1)));
        unsigned pref = sh_prefix;
        for (int i = tid; i < NN_; i += 1024) {
            unsigned kk = keys[i];
            if ((kk & msk) == pref) atomicAdd(&hist[(kk >> (8 * p)) & 255], 1u);
        }
        __syncthreads();
        if (tid == 0) {
            unsigned r = sh_r, c = 0; int b = 0;
            for (b = 255; b >= 0; --b) {
                if (c + hist[b] >= r) break;
                c += hist[b];
            }
            sh_r = r - c;
            sh_prefix = pref | ((unsigned)b << (8 * p));
        }
        __syncthreads();
    }
    unsigned T = sh_prefix;

    {
        unsigned c = 0;
        for (int i = tid; i < NN_; i += 1024) c += (keys[i] > T);
        atomicAdd(&sh_cg, c);
    }
    __syncthreads();
    unsigned ties_needed = KSEL - sh_cg;

    int base = tid * 10;
    int end  = base + 10; if (end > NN_) end = NN_;
    if (base > NN_) base = NN_;

    unsigned tc = 0;
    for (int i = base; i < end; ++i) tc += (keys[i] == T);
    sc[tid] = tc; __syncthreads();
    for (int off = 1; off < 1024; off <<= 1) {
        unsigned v = (tid >= off) ? sc[tid - off] : 0u;
        __syncthreads(); sc[tid] += v; __syncthreads();
    }
    unsigned tie_excl = sc[tid] - tc;
    __syncthreads();

    unsigned scnt = 0;
    {
        unsigned tr = tie_excl;
        for (int i = base; i < end; ++i) {
            unsigned kk = keys[i];
            bool tie = (kk == T);
            bool sel = (kk > T) || (tie && tr < ties_needed);
            tr += tie; scnt += sel;
        }
    }
    sc[tid] = scnt; __syncthreads();
    for (int off = 1; off < 1024; off <<= 1) {
        unsigned v = (tid >= off) ? sc[tid - off] : 0u;
        __syncthreads(); sc[tid] += v; __syncthreads();
    }
    unsigned pos = sc[tid] - scnt;
    {
        unsigned tr = tie_excl;
        for (int i = base; i < end; ++i) {
            unsigned kk = keys[i];
            bool tie = (kk == T);
            bool sel = (kk > T) || (tie && tr < ties_needed);
            tr += tie;
            if (sel) {
                g_topidx[pos] = i;
                out_topidx_f[pos] = (float)i;
                ++pos;
            }
        }
    }
}

// ---------------- K6: x_pool gather (float4) ----------------
__global__ void k_xpool(float* __restrict__ out_x) {
    int t = blockIdx.x * 256 + threadIdx.x;
    if (t >= KSEL * DD_ / 4) return;
    int r  = t >> 5;
    int d4 = (t & 31) * 4;
    float4 v = *(const float4*)&g_h[(size_t)g_topidx[r] * DD_ + d4];
    *(float4*)&out_x[(size_t)r * DD_ + d4] = v;
}

// ---------------- K7: adjacency_pool & motif_pool gathers (8 c's / thread) ----------------
__global__ __launch_bounds__(256) void k_pool(const float* __restrict__ adjacency,
                                              const float* __restrict__ motif,
                                              float* __restrict__ out_adj,
                                              float* __restrict__ out_motif) {
    int r = blockIdx.y;
    int c0 = (blockIdx.x * 256 + threadIdx.x) * 8;
    if (c0 >= KSEL) return;
    int ri = g_topidx[r];
    size_t rb = (size_t)ri * NN_;
    int4 cia = *(const int4*)&g_topidx[c0];
    int4 cib = *(const int4*)&g_topidx[c0 + 4];
    float va[8], vm[8];
    va[0] = __ldg(&adjacency[rb + cia.x]);  vm[0] = __ldg(&motif[rb + cia.x]);
    va[1] = __ldg(&adjacency[rb + cia.y]);  vm[1] = __ldg(&motif[rb + cia.y]);
    va[2] = __ldg(&adjacency[rb + cia.z]);  vm[2] = __ldg(&motif[rb + cia.z]);
    va[3] = __ldg(&adjacency[rb + cia.w]);  vm[3] = __ldg(&motif[rb + cia.w]);
    va[4] = __ldg(&adjacency[rb + cib.x]);  vm[4] = __ldg(&motif[rb + cib.x]);
    va[5] = __ldg(&adjacency[rb + cib.y]);  vm[5] = __ldg(&motif[rb + cib.y]);
    va[6] = __ldg(&adjacency[rb + cib.z]);  vm[6] = __ldg(&motif[rb + cib.z]);
    va[7] = __ldg(&adjacency[rb + cib.w]);  vm[7] = __ldg(&motif[rb + cib.w]);
    size_t dst = (size_t)r * KSEL + c0;
    *(float4*)&out_adj[dst]       = make_float4(va[0], va[1], va[2], va[3]);
    *(float4*)&out_adj[dst + 4]   = make_float4(va[4], va[5], va[6], va[7]);
    *(float4*)&out_motif[dst]     = make_float4(vm[0], vm[1], vm[2], vm[3]);
    *(float4*)&out_motif[dst + 4] = make_float4(vm[4], vm[5], vm[6], vm[7]);
}

// ---------------- launch ----------------
extern "C" void kernel_launch(void* const* d_in, const int* in_sizes, int n_in,
                              void* d_out, int out_size) {
    const float* x       = (const float*)d_in[0];
    const float* adj     = (const float*)d_in[1];
    const float* motif   = (const float*)d_in[2];
    const float* W_gcn   = (const float*)d_in[3];
    const float* b_gcn   = (const float*)d_in[4];
    const float* w_score = (const float*)d_in[5];
    const float* b_score = (const float*)d_in[6];
    float* out = (float*)d_out;

    float* out_x      = out + OFF_XPOOL;
    float* out_adj    = out + OFF_ADJ;
    float* out_motif  = out + OFF_MOTIF;
    float* out_scores = out + OFF_SCORES;
    float* out_tif    = out + OFF_TOPIDX;

    cudaFuncSetAttribute(k_gemm_mma, cudaFuncAttributeMaxDynamicSharedMemorySize, GEMM_SMEM);

    k_deg_part<<<dim3(40, DEG_CHUNKS), 256>>>(motif);
    k_fin<<<104, 256>>>(W_gcn);
    k_z<<<626, 128>>>(x);              // 626 blocks: last zeroes chunk 312 upper half
    k_gemm_mma<<<GRID_GEMM, 256, GEMM_SMEM>>>(motif, b_gcn, w_score, b_score, out_scores);
    k_select<<<1, 1024>>>(out_tif);
    k_xpool<<<625, 256>>>(out_x);
    k_pool<<<dim3(3, KSEL), 256>>>(adj, motif, out_adj, out_motif);
}